// round 5
// baseline (speedup 1.0000x reference)
#include <cuda_runtime.h>
#include <math.h>

#define BB 32
#define TT 1024
#define II 512
#define HH 1024
#define GCTA 128
#define NT 1024

typedef unsigned long long ull;

// ---------------- device global scratch ----------------
__device__ float  g_xT[(size_t)TT * II * BB];          // x transposed [t][i][b]
__device__ float4 g_wp[(size_t)GCTA * 3 * 512 * 8];    // loop weights, pair-packed
__device__ float4 g_wpx[(size_t)128 * 256 * 8];        // x-proj weights, pair-packed
__device__ ull    g_gx[(size_t)TT * HH * BB];          // precomputed x-gates (z,h~) packed
__device__ float  g_h0buf[2][HH * BB];                 // layer0 h, [k/2][b][k%2] interleaved
__device__ float  g_h1buf[2][HH * BB];                 // layer1 h, same layout
__device__ unsigned g_cnt = 0;
__device__ unsigned g_gen = 0;

// ---------------- packed f32x2 helpers ----------------
__device__ __forceinline__ ull dup2(float w) {
    ull r; asm("mov.b64 %0, {%1, %1};" : "=l"(r) : "f"(w)); return r;
}
__device__ __forceinline__ void ffma2(ull &d, ull a, ull b) {
    asm("fma.rn.f32x2 %0, %1, %2, %0;" : "+l"(d) : "l"(a), "l"(b));
}
__device__ __forceinline__ ull add2(ull a, ull b) {
    ull d; asm("add.rn.f32x2 %0, %1, %2;" : "=l"(d) : "l"(a), "l"(b)); return d;
}
__device__ __forceinline__ void unpack2(ull v, float &lo, float &hi) {
    asm("mov.b64 {%0, %1}, %2;" : "=f"(lo), "=f"(hi) : "l"(v));
}

// interleaved h index: float offset for (k, b)
__device__ __forceinline__ int hidx(int k, int b) {
    return (k >> 1) * (BB * 2) + b * 2 + (k & 1);
}

// ---------------- grid barrier ----------------
__device__ __forceinline__ void gridbar() {
    __syncthreads();
    if (threadIdx.x == 0) {
        __threadfence();
        unsigned g = *((volatile unsigned*)&g_gen);
        unsigned a = atomicAdd(&g_cnt, 1u);
        if (a == GCTA - 1u) {
            g_cnt = 0u;
            __threadfence();
            atomicExch(&g_gen, g + 1u);
        } else {
            while (*((volatile unsigned*)&g_gen) == g) { }
        }
        __threadfence();
    }
    __syncthreads();
}

// ---------------- prologue: transpose x (B,T,I) -> xT[t][i][b] ----------------
__global__ void k_transpose_x(const float* __restrict__ x) {
    __shared__ float tile[32][33];
    int t = blockIdx.y;
    int i0 = blockIdx.x * 32;
    int lane = threadIdx.x;
    int row = threadIdx.y;
#pragma unroll
    for (int r = 0; r < 4; r++) {
        int b = row * 4 + r;
        tile[b][lane] = x[((size_t)b * TT + t) * II + i0 + lane];
    }
    __syncthreads();
#pragma unroll
    for (int r = 0; r < 4; r++) {
        int ii = row * 4 + r;
        g_xT[((size_t)t * II + i0 + ii) * BB + lane] = tile[lane][ii];
    }
}

// ---------------- prologue: h0 (2,B,H) -> interleaved ping buffers ----------------
__global__ void k_init_h(const float* __restrict__ h0) {
    int idx = blockIdx.x * blockDim.x + threadIdx.x;
    if (idx < HH * BB) {
        int k = idx / BB;
        int b = idx % BB;
        g_h0buf[0][hidx(k, b)] = h0[(size_t)0 * BB * HH + (size_t)b * HH + k];
        g_h1buf[0][hidx(k, b)] = h0[(size_t)1 * BB * HH + (size_t)b * HH + k];
    }
}

// ---------------- prologue: pack loop weights (pairs interleaved) ----------------
__global__ void k_pack_main(const float* __restrict__ U_z0, const float* __restrict__ W_res0,
                            const float* __restrict__ W_z1, const float* __restrict__ U_z1,
                            const float* __restrict__ W_in1, const float* __restrict__ W_res1)
{
    int idx = blockIdx.x * blockDim.x + threadIdx.x;
    if (idx >= GCTA * 3 * 512 * 8) return;
    int j  = idx & 7;
    int r  = idx >> 3;
    int k2 = r & 511;
    r >>= 9;
    int p   = r % 3;
    int cta = r / 3;
    const float* m0; const float* m1;
    if (p == 0)      { m0 = U_z0; m1 = W_res0; }
    else if (p == 1) { m0 = W_z1; m1 = W_in1;  }
    else             { m0 = U_z1; m1 = W_res1; }
    size_t row = (size_t)(cta * 8 + j) * HH;
    float4 v;
    v.x = m0[row + 2 * k2];     v.y = m1[row + 2 * k2];
    v.z = m0[row + 2 * k2 + 1]; v.w = m1[row + 2 * k2 + 1];
    g_wp[idx] = v;
}

// ---------------- prologue: pack x-projection weights ----------------
__global__ void k_pack_x(const float* __restrict__ W_z0, const float* __restrict__ W_in0) {
    int idx = blockIdx.x * blockDim.x + threadIdx.x;
    if (idx >= 128 * 256 * 8) return;
    int j  = idx & 7;
    int r  = idx >> 3;
    int k2 = r & 255;
    int jb = r >> 8;
    size_t row = (size_t)(jb * 8 + j) * II;
    float4 v;
    v.x = W_z0[row + 2 * k2];     v.y = W_in0[row + 2 * k2];
    v.z = W_z0[row + 2 * k2 + 1]; v.w = W_in0[row + 2 * k2 + 1];
    g_wpx[idx] = v;
}

// ---------------- precompute x-gates: g_gx[t][j][b] = (Wz0.x, Win0.x) packed -----
__global__ void __launch_bounds__(256, 1) k_gx(const float* __restrict__ dummy) {
    extern __shared__ ull sm_gx[];
    ulonglong2* sw = (ulonglong2*)sm_gx;  // 2048 entries (32KB)
    ull*        pr = sm_gx + 4096;        // [w][j][b] 2048 ull (16KB)

    const int jb = blockIdx.x;
    const int tb = blockIdx.y;
    const int tid = threadIdx.x;
    const int w = tid >> 5;
    const int lane = tid & 31;

    const float4* src = g_wpx + (size_t)jb * 2048;
#pragma unroll
    for (int u = 0; u < 8; u++) ((float4*)sw)[tid + u * 256] = src[tid + u * 256];
    __syncthreads();

    for (int tt = 0; tt < 8; tt++) {
        const int t = tb * 8 + tt;
        ull acc[8];
#pragma unroll
        for (int j = 0; j < 8; j++) acc[j] = 0;
        const float* xp = g_xT + (size_t)t * II * BB;
#pragma unroll 4
        for (int u = 0; u < 32; u++) {
            const int k2 = w * 32 + u;
            ull A0 = dup2(__ldg(xp + (2 * k2) * BB + lane));
            ull A1 = dup2(__ldg(xp + (2 * k2 + 1) * BB + lane));
#pragma unroll
            for (int j = 0; j < 8; j++) {
                ulonglong2 wv = sw[k2 * 8 + j];
                ffma2(acc[j], wv.x, A0);
                ffma2(acc[j], wv.y, A1);
            }
        }
#pragma unroll
        for (int j = 0; j < 8; j++) pr[w * 256 + j * 32 + lane] = acc[j];
        __syncthreads();
        if (tid < 256) {
            const int e_j = tid >> 5;
            const int e_b = tid & 31;
            ull s = pr[e_j * 32 + e_b];
#pragma unroll
            for (int ww = 1; ww < 8; ww++) s = add2(s, pr[ww * 256 + e_j * 32 + e_b]);
            g_gx[((size_t)t * HH + jb * 8 + e_j) * BB + e_b] = s;
        }
        __syncthreads();
    }
}

// ---------------- main persistent kernel ----------------
#define SMEM_BYTES (230400)
__global__ void __launch_bounds__(NT, 1) k_esgp(
    const float* __restrict__ b_z0, const float* __restrict__ b_z1,
    float* __restrict__ out)
{
    extern __shared__ ull sm[];
    ulonglong2* sw   = (ulonglong2*)sm;  // 12288 ulonglong2 = 192KB
    ull*   s_red = sm + 24576;           // 4096 ull = 32KB (16 slices of 256)
    float* s_out = (float*)(sm + 28672); // 256 floats

    const int tid = threadIdx.x;
    const int cta = blockIdx.x;
    const int kh = tid >> 5;             // warp 0..31 = k-slice (16 k2 each)
    const int lane = tid & 31;           // = batch b

    // preload weights into SMEM (once)
    {
        const float4* src = g_wp + (size_t)cta * 12288;
        for (int i = tid; i < 12288; i += NT) ((float4*)sw)[i] = src[i];
    }
    __syncthreads();

    // epilogue identity (first 256 threads)
    const int e_j = tid >> 5;            // valid when tid<256: 0..7
    const int e_b = tid & 31;
    const int ejg = cta * 8 + e_j;
    float bz0e = 0.f, bz1e = 0.f;
    if (tid < 256) { bz0e = b_z0[ejg]; bz1e = b_z1[ejg]; }
    const int eh0 = (ejg >> 1) * (BB * 2) + e_b * 2 + (ejg & 1);  // interleaved h addr

    for (int t = 0; t < TT; t++) {
        const int cur = t & 1, nxt = cur ^ 1;
        ull acc[8];

        // ===== layer 0 recurrent: pair0 (U_z0, W_res0) over h0[cur] =====
#pragma unroll
        for (int j = 0; j < 8; j++) acc[j] = 0;
        {
            const float2* hb2 = (const float2*)g_h0buf[cur];
#pragma unroll 4
            for (int u = 0; u < 16; u++) {
                const int k2 = kh * 16 + u;
                float2 hv = __ldcg(hb2 + k2 * BB + lane);
                ull A0 = dup2(hv.x);
                ull A1 = dup2(hv.y);
#pragma unroll
                for (int j = 0; j < 8; j++) {
                    ulonglong2 wv = sw[k2 * 8 + j];
                    ffma2(acc[j], wv.x, A0);
                    ffma2(acc[j], wv.y, A1);
                }
            }
        }
        // ---- two-round reduce: 32 -> 16 -> 1 ----
        if (kh >= 16) {
#pragma unroll
            for (int j = 0; j < 8; j++) s_red[(kh - 16) * 256 + j * 32 + lane] = acc[j];
        }
        __syncthreads();
        if (kh < 16) {
#pragma unroll
            for (int j = 0; j < 8; j++)
                s_red[kh * 256 + j * 32 + lane] = add2(acc[j], s_red[kh * 256 + j * 32 + lane]);
        }
        __syncthreads();
        if (tid < 256) {
            ull s = s_red[e_j * 32 + e_b];
#pragma unroll
            for (int kk = 1; kk < 16; kk++) s = add2(s, s_red[kk * 256 + e_j * 32 + e_b]);
            s = add2(s, __ldg(&g_gx[((size_t)t * HH + ejg) * BB + e_b]));
            float vz, vh; unpack2(s, vz, vh);
            float z   = 1.f / (1.f + expf(-(vz + bz0e)));
            float htl = tanhf(vh);
            float hc  = __ldcg(&g_h0buf[cur][eh0]);
            __stcg(&g_h0buf[nxt][eh0], (1.f - z) * hc + z * htl);
        }
        gridbar();   // the only grid barrier per step

        // ===== layer 1: pair1 (W_z1,W_in1) over h0[nxt], pair2 (U_z1,W_res1) over h1[cur]
#pragma unroll
        for (int j = 0; j < 8; j++) acc[j] = 0;
        {
            const float2* pb2 = (const float2*)g_h0buf[nxt];
            const float2* qb2 = (const float2*)g_h1buf[cur];
#pragma unroll 4
            for (int u = 0; u < 16; u++) {
                const int k2 = kh * 16 + u;
                float2 pv = __ldcg(pb2 + k2 * BB + lane);
                float2 qv = __ldcg(qb2 + k2 * BB + lane);
                ull A0 = dup2(pv.x), A1 = dup2(pv.y);
                ull B0 = dup2(qv.x), B1 = dup2(qv.y);
#pragma unroll
                for (int j = 0; j < 8; j++) {
                    ulonglong2 w1 = sw[4096 + k2 * 8 + j];
                    ulonglong2 w2 = sw[8192 + k2 * 8 + j];
                    ffma2(acc[j], w1.x, A0);
                    ffma2(acc[j], w1.y, A1);
                    ffma2(acc[j], w2.x, B0);
                    ffma2(acc[j], w2.y, B1);
                }
            }
        }
        if (kh >= 16) {
#pragma unroll
            for (int j = 0; j < 8; j++) s_red[(kh - 16) * 256 + j * 32 + lane] = acc[j];
        }
        __syncthreads();
        if (kh < 16) {
#pragma unroll
            for (int j = 0; j < 8; j++)
                s_red[kh * 256 + j * 32 + lane] = add2(acc[j], s_red[kh * 256 + j * 32 + lane]);
        }
        __syncthreads();
        if (tid < 256) {
            ull s = s_red[e_j * 32 + e_b];
#pragma unroll
            for (int kk = 1; kk < 16; kk++) s = add2(s, s_red[kk * 256 + e_j * 32 + e_b]);
            float vz, vh; unpack2(s, vz, vh);
            float z   = 1.f / (1.f + expf(-(vz + bz1e)));
            float htl = tanhf(vh);
            float hc  = __ldcg(&g_h1buf[cur][eh0]);
            float hn  = (1.f - z) * hc + z * htl;
            __stcg(&g_h1buf[nxt][eh0], hn);
            s_out[e_j * 32 + e_b] = hn;
        }
        __syncthreads();
        if (tid < 256) {   // coalesced-by-j output write: out[b][t][cta*8+j]
            int b = tid >> 3, j = tid & 7;
            out[((size_t)b * TT + t) * HH + cta * 8 + j] = s_out[j * 32 + b];
        }
        __syncthreads();   // protect s_red/s_out reuse next step
    }

    // ---- h_n tail: final state parity 0 (T even) ----
    if (tid < 256) {
        const int jg2 = cta * 8 + e_j;
        const int hoff = (jg2 >> 1) * (BB * 2) + e_b * 2 + (jg2 & 1);
        const size_t base = (size_t)BB * TT * HH;
        out[base + (size_t)e_b * HH + jg2] = __ldcg(&g_h0buf[0][hoff]);
        out[base + (size_t)BB * HH + (size_t)e_b * HH + jg2] = __ldcg(&g_h1buf[0][hoff]);
    }
}

// ---------------- launcher ----------------
extern "C" void kernel_launch(void* const* d_in, const int* in_sizes, int n_in,
                              void* d_out, int out_size) {
    const float* x      = (const float*)d_in[0];
    const float* h0     = (const float*)d_in[1];
    const float* W_in0  = (const float*)d_in[2];
    const float* W_res0 = (const float*)d_in[3];
    const float* W_z0   = (const float*)d_in[4];
    const float* U_z0   = (const float*)d_in[5];
    const float* b_z0   = (const float*)d_in[6];
    const float* W_in1  = (const float*)d_in[7];
    const float* W_res1 = (const float*)d_in[8];
    const float* W_z1   = (const float*)d_in[9];
    const float* U_z1   = (const float*)d_in[10];
    const float* b_z1   = (const float*)d_in[11];
    float* out = (float*)d_out;

    static int configured = 0;
    if (!configured) {
        cudaFuncSetAttribute(k_esgp, cudaFuncAttributeMaxDynamicSharedMemorySize, SMEM_BYTES);
        cudaFuncSetAttribute(k_gx, cudaFuncAttributeMaxDynamicSharedMemorySize, 49152);
        configured = 1;
    }

    dim3 tb(32, 8);
    dim3 tg(II / 32, TT);
    k_transpose_x<<<tg, tb>>>(x);
    k_init_h<<<(HH * BB + 255) / 256, 256>>>(h0);
    k_pack_main<<<(GCTA * 3 * 512 * 8 + 255) / 256, 256>>>(U_z0, W_res0, W_z1, U_z1, W_in1, W_res1);
    k_pack_x<<<(128 * 256 * 8 + 255) / 256, 256>>>(W_z0, W_in0);
    k_gx<<<dim3(128, 128), 256, 49152>>>(x);
    k_esgp<<<GCTA, NT, SMEM_BYTES>>>(b_z0, b_z1, out);
}